// round 4
// baseline (speedup 1.0000x reference)
#include <cuda_runtime.h>
#include <cstdint>

#define NP   100000
#define RREL 3
#define NE   1600000
#define EPC  500000
#define FIN  128
#define FH   64

// ---------------- device scratch (static, allocation-free) ----------------
__device__ int   g_cnt[6 * NP];            // [0:3N) src counts, [3N:6N) dst counts
__device__ float g_rs [6 * NP];            // rsqrt(max(count,1)) same layout
__device__ float g_h  [RREL * NP * FH];    // per-relation projected features (reused for layer 2)
__device__ float g_agg1[NP * FH];          // layer-1 accumulation (scaled at scatter time)
__device__ float g_h1 [NP * FH];           // relu(hetero_conv1)
__device__ float g_agg2[NP * 32];          // layer-2 accumulation (mu[0:16] | log_std[16:32])

// ---------------- small helpers ----------------
__device__ __forceinline__ void red4(float* p, float a, float b, float c, float d) {
    asm volatile("red.global.add.v4.f32 [%0], {%1,%2,%3,%4};"
                 :: "l"(p), "f"(a), "f"(b), "f"(c), "f"(d) : "memory");
}

// Threefry-2x32, 20 rounds, key = (0, 42)  (jax.random.key(42))
__device__ __forceinline__ void threefry_0_42(uint32_t x0, uint32_t x1,
                                              uint32_t& o0, uint32_t& o1) {
    const uint32_t k0 = 0u, k1 = 42u, k2 = 0x1BD11BDAu ^ 0u ^ 42u;
    x0 += k0; x1 += k1;
#define TF_RND(Rv) { x0 += x1; x1 = __funnelshift_l(x1, x1, (Rv)); x1 ^= x0; }
    TF_RND(13) TF_RND(15) TF_RND(26) TF_RND(6)   x0 += k1; x1 += k2 + 1u;
    TF_RND(17) TF_RND(29) TF_RND(16) TF_RND(24)  x0 += k2; x1 += k0 + 2u;
    TF_RND(13) TF_RND(15) TF_RND(26) TF_RND(6)   x0 += k0; x1 += k1 + 3u;
    TF_RND(17) TF_RND(29) TF_RND(16) TF_RND(24)  x0 += k1; x1 += k2 + 4u;
    TF_RND(13) TF_RND(15) TF_RND(26) TF_RND(6)   x0 += k2; x1 += k0 + 5u;
#undef TF_RND
    o0 = x0; o1 = x1;
}

// bits -> jax-style standard normal (uniform in [lo,1) then sqrt(2)*erfinv)
__device__ __forceinline__ float jax_normal(uint32_t bits) {
    const float LO = -0.99999994f;                 // nextafter(-1,0)
    float f = __uint_as_float((bits >> 9) | 0x3f800000u) - 1.0f;  // [0,1)
    float u = fmaxf(f * 2.0f + LO, LO);            // (hi-lo) rounds to exactly 2.0f
    return 1.41421356237309515f * erfinvf(u);
}

// ---------------- kernels ----------------
__global__ void zero_kernel() {
    int i = blockIdx.x * 256 + threadIdx.x;
    if (i < NP * FH) g_agg1[i] = 0.f;
    if (i < NP * 32) g_agg2[i] = 0.f;
    if (i < 6 * NP)  g_cnt[i]  = 0;
}

__global__ void deg_kernel(const int* __restrict__ es, const int* __restrict__ ed) {
    int i = blockIdx.x * 256 + threadIdx.x;
    if (i >= RREL * NE) return;
    int r = i / NE;
    atomicAdd(&g_cnt[r * NP + es[i]], 1);
    atomicAdd(&g_cnt[3 * NP + r * NP + ed[i]], 1);
}

__global__ void rs_kernel() {
    int i = blockIdx.x * 256 + threadIdx.x;
    if (i < 6 * NP) g_rs[i] = rsqrtf(fmaxf((float)g_cnt[i], 1.0f));
}

// layer-1 projection: g_h[r][m][0:64] = (x[m] * rsqrt(deg_out_r[m])) @ W0[r]
// STATIC smem only (25 KB): 128-row tile, K processed in 4 chunks of 32.
__global__ void __launch_bounds__(128) proj1_kernel(const float* __restrict__ x,
                                                    const float* __restrict__ W0) {
    __shared__ float xs[128 * 33];   // 128 rows x 32-k chunk, stride 33 (conflict-free)
    __shared__ float Ws[32 * 64];    // k-chunk x 64 cols
    const int r = blockIdx.y, t = threadIdx.x, m0 = blockIdx.x * 128;
    const int lane = t & 31, c0 = (t >> 5) * 16;

    float4 acc[4][4];
#pragma unroll
    for (int j = 0; j < 4; ++j)
#pragma unroll
        for (int q = 0; q < 4; ++q) acc[j][q] = make_float4(0.f, 0.f, 0.f, 0.f);

    const float4* x4 = (const float4*)x;
    const float* W = W0 + r * FIN * FH;

    for (int c = 0; c < 4; ++c) {
        // stage x[:, c*32 : c*32+32], pre-scaled by rsqrt(deg_out)
#pragma unroll
        for (int it = 0; it < 8; ++it) {
            int idx = t + it * 128;
            int row = idx >> 3, q = idx & 7;        // 128 rows x 8 float4
            int m = m0 + row;
            float4 v = make_float4(0.f, 0.f, 0.f, 0.f); float s = 0.f;
            if (m < NP) { v = x4[m * 32 + c * 8 + q]; s = g_rs[r * NP + m]; }
            float* p = &xs[row * 33 + q * 4];
            p[0] = v.x * s; p[1] = v.y * s; p[2] = v.z * s; p[3] = v.w * s;
        }
        // stage W[c*32 : c*32+32, :]
#pragma unroll
        for (int i = t; i < 32 * 64; i += 128) Ws[i] = W[c * 32 * 64 + i];
        __syncthreads();

        for (int k = 0; k < 32; ++k) {
            float4 w0 = *(const float4*)&Ws[k * 64 + c0];
            float4 w1 = *(const float4*)&Ws[k * 64 + c0 + 4];
            float4 w2 = *(const float4*)&Ws[k * 64 + c0 + 8];
            float4 w3 = *(const float4*)&Ws[k * 64 + c0 + 12];
#pragma unroll
            for (int j = 0; j < 4; ++j) {
                float xv = xs[(lane + 32 * j) * 33 + k];
                acc[j][0].x = fmaf(xv, w0.x, acc[j][0].x);
                acc[j][0].y = fmaf(xv, w0.y, acc[j][0].y);
                acc[j][0].z = fmaf(xv, w0.z, acc[j][0].z);
                acc[j][0].w = fmaf(xv, w0.w, acc[j][0].w);
                acc[j][1].x = fmaf(xv, w1.x, acc[j][1].x);
                acc[j][1].y = fmaf(xv, w1.y, acc[j][1].y);
                acc[j][1].z = fmaf(xv, w1.z, acc[j][1].z);
                acc[j][1].w = fmaf(xv, w1.w, acc[j][1].w);
                acc[j][2].x = fmaf(xv, w2.x, acc[j][2].x);
                acc[j][2].y = fmaf(xv, w2.y, acc[j][2].y);
                acc[j][2].z = fmaf(xv, w2.z, acc[j][2].z);
                acc[j][2].w = fmaf(xv, w2.w, acc[j][2].w);
                acc[j][3].x = fmaf(xv, w3.x, acc[j][3].x);
                acc[j][3].y = fmaf(xv, w3.y, acc[j][3].y);
                acc[j][3].z = fmaf(xv, w3.z, acc[j][3].z);
                acc[j][3].w = fmaf(xv, w3.w, acc[j][3].w);
            }
        }
        __syncthreads();
    }

#pragma unroll
    for (int j = 0; j < 4; ++j) {
        int m = m0 + lane + 32 * j;
        if (m >= NP) continue;
        float4* o = (float4*)&g_h[(r * NP + m) * FH + c0];
        o[0] = acc[j][0]; o[1] = acc[j][1]; o[2] = acc[j][2]; o[3] = acc[j][3];
    }
}

// layer-1 scatter: agg1[d] += rsqrt(deg_in_r[d]) * h_r[s], 16 lanes/edge (float4 each)
__global__ void scatter1_kernel(const int* __restrict__ es, const int* __restrict__ ed) {
    int idx = blockIdx.x * 256 + threadIdx.x;
    if (idx >= RREL * NE * 16) return;
    int e = idx >> 4, l = idx & 15;
    int r = e / NE;
    int s = es[e], d = ed[e];
    float sc = g_rs[3 * NP + r * NP + d];
    float4 v = *(const float4*)&g_h[(r * NP + s) * FH + l * 4];
    red4(&g_agg1[d * FH + l * 4], v.x * sc, v.y * sc, v.z * sc, v.w * sc);
}

__global__ void relu_kernel(const float* __restrict__ b0) {
    int i = blockIdx.x * 256 + threadIdx.x;
    if (i >= NP * FH) return;
    int j = i & 63;
    float bs = b0[j] + b0[FH + j] + b0[2 * FH + j];
    g_h1[i] = fmaxf(g_agg1[i] + bs, 0.f);
}

// layer-2 projection: g_h[r][m][0:16]=(h1*s)@W_mu[r], [16:32]=(h1*s)@W_ls[r]
__global__ void __launch_bounds__(128) proj2_kernel(const float* __restrict__ Wmu,
                                                    const float* __restrict__ Wls) {
    __shared__ float xs[128 * 65];
    __shared__ float Ws[64 * 32];
    const int r = blockIdx.y, t = threadIdx.x, m0 = blockIdx.x * 128;

    for (int i = t; i < 64 * 16; i += 128) {
        int k = i >> 4, c = i & 15;
        Ws[k * 32 + c]      = Wmu[r * 1024 + i];
        Ws[k * 32 + 16 + c] = Wls[r * 1024 + i];
    }
    const float4* h4 = (const float4*)g_h1;
#pragma unroll 4
    for (int it = 0; it < 16; ++it) {
        int idx = t + it * 128;
        int row = idx >> 4, q = idx & 15;
        int m = m0 + row;
        float4 v = make_float4(0.f, 0.f, 0.f, 0.f); float s = 0.f;
        if (m < NP) { v = h4[m * 16 + q]; s = g_rs[r * NP + m]; }
        float* p = &xs[row * 65 + q * 4];
        p[0] = v.x * s; p[1] = v.y * s; p[2] = v.z * s; p[3] = v.w * s;
    }
    __syncthreads();

    const int lane = t & 31, c0 = (t >> 5) * 8;
    float4 acc[4][2];
#pragma unroll
    for (int j = 0; j < 4; ++j) {
        acc[j][0] = make_float4(0.f, 0.f, 0.f, 0.f);
        acc[j][1] = make_float4(0.f, 0.f, 0.f, 0.f);
    }

    for (int k = 0; k < 64; ++k) {
        float4 w0 = *(const float4*)&Ws[k * 32 + c0];
        float4 w1 = *(const float4*)&Ws[k * 32 + c0 + 4];
#pragma unroll
        for (int j = 0; j < 4; ++j) {
            float xv = xs[(lane + 32 * j) * 65 + k];
            acc[j][0].x = fmaf(xv, w0.x, acc[j][0].x);
            acc[j][0].y = fmaf(xv, w0.y, acc[j][0].y);
            acc[j][0].z = fmaf(xv, w0.z, acc[j][0].z);
            acc[j][0].w = fmaf(xv, w0.w, acc[j][0].w);
            acc[j][1].x = fmaf(xv, w1.x, acc[j][1].x);
            acc[j][1].y = fmaf(xv, w1.y, acc[j][1].y);
            acc[j][1].z = fmaf(xv, w1.z, acc[j][1].z);
            acc[j][1].w = fmaf(xv, w1.w, acc[j][1].w);
        }
    }
#pragma unroll
    for (int j = 0; j < 4; ++j) {
        int m = m0 + lane + 32 * j;
        if (m >= NP) continue;
        float4* o = (float4*)&g_h[(r * NP + m) * 32 + c0];
        o[0] = acc[j][0]; o[1] = acc[j][1];
    }
}

// layer-2 scatter: 8 lanes/edge over 32 dims
__global__ void scatter2_kernel(const int* __restrict__ es, const int* __restrict__ ed) {
    int idx = blockIdx.x * 256 + threadIdx.x;
    if (idx >= RREL * NE * 8) return;
    int e = idx >> 3, l = idx & 7;
    int r = e / NE;
    int s = es[e], d = ed[e];
    float sc = g_rs[3 * NP + r * NP + d];
    float4 v = *(const float4*)&g_h[(r * NP + s) * 32 + l * 4];
    red4(&g_agg2[d * 32 + l * 4], v.x * sc, v.y * sc, v.z * sc, v.w * sc);
}

// VGAE head with PARTITIONABLE threefry (modern JAX default):
// counts = iota(uint64); (b1,b2) = threefry(key=(0,42), (hi32=0, lo32=i));
// 32-bit output = b1 ^ b2  (XOR-fold, jax/_src/prng.py partitionable path)
__global__ void final_kernel(const float* __restrict__ bmu, const float* __restrict__ bls,
                             float* __restrict__ out) {
    int i = blockIdx.x * 256 + threadIdx.x;
    if (i >= NP * 16) return;
    uint32_t o0, o1;
    threefry_0_42(0u, (uint32_t)i, o0, o1);
    int n = i >> 4, f = i & 15;
    float bm = bmu[f] + bmu[16 + f] + bmu[32 + f];
    float bl = bls[f] + bls[16 + f] + bls[32 + f];
    float mean = g_agg2[n * 32 + f] + bm;
    float ls   = g_agg2[n * 32 + 16 + f] + bl;
    out[1000000 + i] = mean + jax_normal(o0 ^ o1) * expf(ls);
}

__global__ void score_kernel(const int* __restrict__ ps, const int* __restrict__ pd,
                             const int* __restrict__ ns, const int* __restrict__ nd,
                             float* __restrict__ out) {
    int i = blockIdx.x * 256 + threadIdx.x;
    if (i >= 2 * EPC) return;
    int s, d;
    if (i < EPC) { s = ps[i]; d = pd[i]; }
    else         { s = ns[i - EPC]; d = nd[i - EPC]; }
    const float4* h4 = (const float4*)(out + 1000000);
    float acc = 0.f;
#pragma unroll
    for (int q = 0; q < 4; ++q) {
        float4 a = h4[s * 4 + q], b = h4[d * 4 + q];
        acc += a.x * b.x + a.y * b.y + a.z * b.z + a.w * b.w;
    }
    out[i] = acc;
}

// ---------------- launch ----------------
extern "C" void kernel_launch(void* const* d_in, const int* in_sizes, int n_in,
                              void* d_out, int out_size) {
    const float* x   = (const float*)d_in[0];
    const float* W0  = (const float*)d_in[1];
    const float* b0  = (const float*)d_in[2];
    const float* Wmu = (const float*)d_in[3];
    const float* bmu = (const float*)d_in[4];
    const float* Wls = (const float*)d_in[5];
    const float* bls = (const float*)d_in[6];
    const int*   es  = (const int*)d_in[7];
    const int*   ed  = (const int*)d_in[8];
    const int*   ps  = (const int*)d_in[9];
    const int*   pd  = (const int*)d_in[10];
    const int*   ns  = (const int*)d_in[11];
    const int*   nd  = (const int*)d_in[12];
    float* out = (float*)d_out;

    const int MBLK = (NP + 127) / 128;  // 782

    zero_kernel    <<<(NP * FH + 255) / 256, 256>>>();
    deg_kernel     <<<(RREL * NE + 255) / 256, 256>>>(es, ed);
    rs_kernel      <<<(6 * NP + 255) / 256, 256>>>();
    proj1_kernel   <<<dim3(MBLK, RREL), 128>>>(x, W0);
    scatter1_kernel<<<(RREL * NE * 16) / 256, 256>>>(es, ed);
    relu_kernel    <<<(NP * FH + 255) / 256, 256>>>(b0);
    proj2_kernel   <<<dim3(MBLK, RREL), 128>>>(Wmu, Wls);
    scatter2_kernel<<<(RREL * NE * 8) / 256, 256>>>(es, ed);
    final_kernel   <<<(NP * 16 + 255) / 256, 256>>>(bmu, bls, out);
    score_kernel   <<<(2 * EPC + 255) / 256, 256>>>(ps, pd, ns, nd, out);
}

// round 5
// speedup vs baseline: 1.4115x; 1.4115x over previous
#include <cuda_runtime.h>
#include <cstdint>

#define NP   100000
#define RREL 3
#define NE   1600000
#define EPC  500000
#define FIN  128
#define FH   64
#define NDST (RREL * NP)          // 300000 scanned rows
#define SCAN_BLK 512
#define SCAN_NB  ((NDST + SCAN_BLK - 1) / SCAN_BLK)   // 586

// ---------------- device scratch (static, allocation-free) ----------------
__device__ int   g_cnt[6 * NP];          // [0:3N) src counts, [3N:6N) dst counts
__device__ float g_rs [6 * NP];          // rsqrt(max(count,1)) same layout
__device__ float g_h  [RREL * NP * FH];  // per-relation projected features (reused for layer 2)
__device__ float g_h1 [NP * FH];         // relu(hetero_conv1)
__device__ int   g_rowptr[NDST + 1];     // CSR row pointers (relations concatenated)
__device__ int   g_cursor[NDST];         // fill cursors
__device__ int   g_csr[RREL * NE];       // src node per in-edge, grouped by (rel,dst)
__device__ int   g_bsum[SCAN_NB];        // scan spine

// Threefry-2x32, 20 rounds, key = (0, 42)  (jax.random.key(42))
__device__ __forceinline__ void threefry_0_42(uint32_t x0, uint32_t x1,
                                              uint32_t& o0, uint32_t& o1) {
    const uint32_t k0 = 0u, k1 = 42u, k2 = 0x1BD11BDAu ^ 0u ^ 42u;
    x0 += k0; x1 += k1;
#define TF_RND(Rv) { x0 += x1; x1 = __funnelshift_l(x1, x1, (Rv)); x1 ^= x0; }
    TF_RND(13) TF_RND(15) TF_RND(26) TF_RND(6)   x0 += k1; x1 += k2 + 1u;
    TF_RND(17) TF_RND(29) TF_RND(16) TF_RND(24)  x0 += k2; x1 += k0 + 2u;
    TF_RND(13) TF_RND(15) TF_RND(26) TF_RND(6)   x0 += k0; x1 += k1 + 3u;
    TF_RND(17) TF_RND(29) TF_RND(16) TF_RND(24)  x0 += k1; x1 += k2 + 4u;
    TF_RND(13) TF_RND(15) TF_RND(26) TF_RND(6)   x0 += k2; x1 += k0 + 5u;
#undef TF_RND
    o0 = x0; o1 = x1;
}

// bits -> jax-style standard normal (uniform in [lo,1) then sqrt(2)*erfinv)
__device__ __forceinline__ float jax_normal(uint32_t bits) {
    const float LO = -0.99999994f;
    float f = __uint_as_float((bits >> 9) | 0x3f800000u) - 1.0f;
    float u = fmaxf(f * 2.0f + LO, LO);
    return 1.41421356237309515f * erfinvf(u);
}

// ---------------- setup kernels ----------------
__global__ void zero_kernel() {
    int i = blockIdx.x * 256 + threadIdx.x;
    if (i < 6 * NP) g_cnt[i] = 0;
}

__global__ void deg_kernel(const int* __restrict__ es, const int* __restrict__ ed) {
    int i = blockIdx.x * 256 + threadIdx.x;
    if (i >= RREL * NE) return;
    int r = i / NE;
    atomicAdd(&g_cnt[r * NP + es[i]], 1);
    atomicAdd(&g_cnt[3 * NP + r * NP + ed[i]], 1);
}

__global__ void rs_kernel() {
    int i = blockIdx.x * 256 + threadIdx.x;
    if (i < 6 * NP) g_rs[i] = rsqrtf(fmaxf((float)g_cnt[i], 1.0f));
}

// ---- 3-kernel exclusive scan over dst counts (g_cnt[3NP : 6NP)) ----
__global__ void scan_blocksum_kernel() {
    __shared__ int sm[SCAN_BLK];
    int i = blockIdx.x * SCAN_BLK + threadIdx.x;
    int v = (i < NDST) ? g_cnt[3 * NP + i] : 0;
    sm[threadIdx.x] = v;
    __syncthreads();
    for (int off = SCAN_BLK / 2; off > 0; off >>= 1) {
        if (threadIdx.x < off) sm[threadIdx.x] += sm[threadIdx.x + off];
        __syncthreads();
    }
    if (threadIdx.x == 0) g_bsum[blockIdx.x] = sm[0];
}

__global__ void scan_spine_kernel() {   // 1 block of 1024, exclusive scan of SCAN_NB sums
    __shared__ int sm[1024];
    int t = threadIdx.x;
    int v = (t < SCAN_NB) ? g_bsum[t] : 0;
    sm[t] = v;
    __syncthreads();
    for (int off = 1; off < 1024; off <<= 1) {
        int add = (t >= off) ? sm[t - off] : 0;
        __syncthreads();
        sm[t] += add;
        __syncthreads();
    }
    if (t < SCAN_NB) g_bsum[t] = sm[t] - v;   // exclusive
}

__global__ void scan_apply_kernel() {
    __shared__ int sm[SCAN_BLK];
    int i = blockIdx.x * SCAN_BLK + threadIdx.x;
    int t = threadIdx.x;
    int v = (i < NDST) ? g_cnt[3 * NP + i] : 0;
    sm[t] = v;
    __syncthreads();
    for (int off = 1; off < SCAN_BLK; off <<= 1) {
        int add = (t >= off) ? sm[t - off] : 0;
        __syncthreads();
        sm[t] += add;
        __syncthreads();
    }
    if (i < NDST) {
        int excl = g_bsum[blockIdx.x] + sm[t] - v;
        g_rowptr[i] = excl;
        g_cursor[i] = excl;
    }
    if (i == 0) g_rowptr[NDST] = RREL * NE;
}

__global__ void fill_csr_kernel(const int* __restrict__ es, const int* __restrict__ ed) {
    int i = blockIdx.x * 256 + threadIdx.x;
    if (i >= RREL * NE) return;
    int r = i / NE;
    int pos = atomicAdd(&g_cursor[r * NP + ed[i]], 1);
    g_csr[pos] = es[i];
}

// ---------------- layer-1 projection (unchanged from R4) ----------------
__global__ void __launch_bounds__(128) proj1_kernel(const float* __restrict__ x,
                                                    const float* __restrict__ W0) {
    __shared__ float xs[128 * 33];
    __shared__ float Ws[32 * 64];
    const int r = blockIdx.y, t = threadIdx.x, m0 = blockIdx.x * 128;
    const int lane = t & 31, c0 = (t >> 5) * 16;

    float4 acc[4][4];
#pragma unroll
    for (int j = 0; j < 4; ++j)
#pragma unroll
        for (int q = 0; q < 4; ++q) acc[j][q] = make_float4(0.f, 0.f, 0.f, 0.f);

    const float4* x4 = (const float4*)x;
    const float* W = W0 + r * FIN * FH;

    for (int c = 0; c < 4; ++c) {
#pragma unroll
        for (int it = 0; it < 8; ++it) {
            int idx = t + it * 128;
            int row = idx >> 3, q = idx & 7;
            int m = m0 + row;
            float4 v = make_float4(0.f, 0.f, 0.f, 0.f); float s = 0.f;
            if (m < NP) { v = x4[m * 32 + c * 8 + q]; s = g_rs[r * NP + m]; }
            float* p = &xs[row * 33 + q * 4];
            p[0] = v.x * s; p[1] = v.y * s; p[2] = v.z * s; p[3] = v.w * s;
        }
#pragma unroll
        for (int i = t; i < 32 * 64; i += 128) Ws[i] = W[c * 32 * 64 + i];
        __syncthreads();

        for (int k = 0; k < 32; ++k) {
            float4 w0 = *(const float4*)&Ws[k * 64 + c0];
            float4 w1 = *(const float4*)&Ws[k * 64 + c0 + 4];
            float4 w2 = *(const float4*)&Ws[k * 64 + c0 + 8];
            float4 w3 = *(const float4*)&Ws[k * 64 + c0 + 12];
#pragma unroll
            for (int j = 0; j < 4; ++j) {
                float xv = xs[(lane + 32 * j) * 33 + k];
                acc[j][0].x = fmaf(xv, w0.x, acc[j][0].x);
                acc[j][0].y = fmaf(xv, w0.y, acc[j][0].y);
                acc[j][0].z = fmaf(xv, w0.z, acc[j][0].z);
                acc[j][0].w = fmaf(xv, w0.w, acc[j][0].w);
                acc[j][1].x = fmaf(xv, w1.x, acc[j][1].x);
                acc[j][1].y = fmaf(xv, w1.y, acc[j][1].y);
                acc[j][1].z = fmaf(xv, w1.z, acc[j][1].z);
                acc[j][1].w = fmaf(xv, w1.w, acc[j][1].w);
                acc[j][2].x = fmaf(xv, w2.x, acc[j][2].x);
                acc[j][2].y = fmaf(xv, w2.y, acc[j][2].y);
                acc[j][2].z = fmaf(xv, w2.z, acc[j][2].z);
                acc[j][2].w = fmaf(xv, w2.w, acc[j][2].w);
                acc[j][3].x = fmaf(xv, w3.x, acc[j][3].x);
                acc[j][3].y = fmaf(xv, w3.y, acc[j][3].y);
                acc[j][3].z = fmaf(xv, w3.z, acc[j][3].z);
                acc[j][3].w = fmaf(xv, w3.w, acc[j][3].w);
            }
        }
        __syncthreads();
    }

#pragma unroll
    for (int j = 0; j < 4; ++j) {
        int m = m0 + lane + 32 * j;
        if (m >= NP) continue;
        float4* o = (float4*)&g_h[(r * NP + m) * FH + c0];
        o[0] = acc[j][0]; o[1] = acc[j][1]; o[2] = acc[j][2]; o[3] = acc[j][3];
    }
}

// ---------------- layer-1 gather (pull, CSR) — fuses scale+bias+relu ----------------
__global__ void __launch_bounds__(256) gather1_kernel(const float* __restrict__ b0) {
    int w = (blockIdx.x * 256 + threadIdx.x) >> 5;   // dst node
    int lane = threadIdx.x & 31;
    if (w >= NP) return;
    float a0 = 0.f, a1 = 0.f;
#pragma unroll
    for (int r = 0; r < RREL; ++r) {
        int beg = g_rowptr[r * NP + w];
        int end = g_rowptr[r * NP + w + 1];
        float sc = g_rs[3 * NP + r * NP + w];
        const float* hb = g_h + (size_t)r * NP * FH;
        float s0 = 0.f, s1 = 0.f;
        int e = beg;
        for (; e + 4 <= end; e += 4) {
            int i0 = g_csr[e], i1 = g_csr[e + 1], i2 = g_csr[e + 2], i3 = g_csr[e + 3];
            float v0a = hb[i0 * FH + lane],      v0b = hb[i0 * FH + 32 + lane];
            float v1a = hb[i1 * FH + lane],      v1b = hb[i1 * FH + 32 + lane];
            float v2a = hb[i2 * FH + lane],      v2b = hb[i2 * FH + 32 + lane];
            float v3a = hb[i3 * FH + lane],      v3b = hb[i3 * FH + 32 + lane];
            s0 += (v0a + v1a) + (v2a + v3a);
            s1 += (v0b + v1b) + (v2b + v3b);
        }
        for (; e < end; ++e) {
            int s = g_csr[e];
            s0 += hb[s * FH + lane];
            s1 += hb[s * FH + 32 + lane];
        }
        a0 = fmaf(sc, s0, a0);
        a1 = fmaf(sc, s1, a1);
    }
    float bs0 = b0[lane]      + b0[FH + lane]      + b0[2 * FH + lane];
    float bs1 = b0[32 + lane] + b0[FH + 32 + lane] + b0[2 * FH + 32 + lane];
    g_h1[w * FH + lane]      = fmaxf(a0 + bs0, 0.f);
    g_h1[w * FH + 32 + lane] = fmaxf(a1 + bs1, 0.f);
}

// ---------------- layer-2 projection (unchanged from R4) ----------------
__global__ void __launch_bounds__(128) proj2_kernel(const float* __restrict__ Wmu,
                                                    const float* __restrict__ Wls) {
    __shared__ float xs[128 * 65];
    __shared__ float Ws[64 * 32];
    const int r = blockIdx.y, t = threadIdx.x, m0 = blockIdx.x * 128;

    for (int i = t; i < 64 * 16; i += 128) {
        int k = i >> 4, c = i & 15;
        Ws[k * 32 + c]      = Wmu[r * 1024 + i];
        Ws[k * 32 + 16 + c] = Wls[r * 1024 + i];
    }
    const float4* h4 = (const float4*)g_h1;
#pragma unroll 4
    for (int it = 0; it < 16; ++it) {
        int idx = t + it * 128;
        int row = idx >> 4, q = idx & 15;
        int m = m0 + row;
        float4 v = make_float4(0.f, 0.f, 0.f, 0.f); float s = 0.f;
        if (m < NP) { v = h4[m * 16 + q]; s = g_rs[r * NP + m]; }
        float* p = &xs[row * 65 + q * 4];
        p[0] = v.x * s; p[1] = v.y * s; p[2] = v.z * s; p[3] = v.w * s;
    }
    __syncthreads();

    const int lane = t & 31, c0 = (t >> 5) * 8;
    float4 acc[4][2];
#pragma unroll
    for (int j = 0; j < 4; ++j) {
        acc[j][0] = make_float4(0.f, 0.f, 0.f, 0.f);
        acc[j][1] = make_float4(0.f, 0.f, 0.f, 0.f);
    }

    for (int k = 0; k < 64; ++k) {
        float4 w0 = *(const float4*)&Ws[k * 32 + c0];
        float4 w1 = *(const float4*)&Ws[k * 32 + c0 + 4];
#pragma unroll
        for (int j = 0; j < 4; ++j) {
            float xv = xs[(lane + 32 * j) * 65 + k];
            acc[j][0].x = fmaf(xv, w0.x, acc[j][0].x);
            acc[j][0].y = fmaf(xv, w0.y, acc[j][0].y);
            acc[j][0].z = fmaf(xv, w0.z, acc[j][0].z);
            acc[j][0].w = fmaf(xv, w0.w, acc[j][0].w);
            acc[j][1].x = fmaf(xv, w1.x, acc[j][1].x);
            acc[j][1].y = fmaf(xv, w1.y, acc[j][1].y);
            acc[j][1].z = fmaf(xv, w1.z, acc[j][1].z);
            acc[j][1].w = fmaf(xv, w1.w, acc[j][1].w);
        }
    }
#pragma unroll
    for (int j = 0; j < 4; ++j) {
        int m = m0 + lane + 32 * j;
        if (m >= NP) continue;
        float4* o = (float4*)&g_h[(r * NP + m) * 32 + c0];
        o[0] = acc[j][0]; o[1] = acc[j][1];
    }
}

// ---------------- layer-2 gather — fuses bias + VGAE reparameterization ----------------
__global__ void __launch_bounds__(256) gather2_kernel(const float* __restrict__ bmu,
                                                      const float* __restrict__ bls,
                                                      float* __restrict__ out) {
    int w = (blockIdx.x * 256 + threadIdx.x) >> 5;   // dst node
    int lane = threadIdx.x & 31;
    if (w >= NP) return;
    float acc = 0.f;
#pragma unroll
    for (int r = 0; r < RREL; ++r) {
        int beg = g_rowptr[r * NP + w];
        int end = g_rowptr[r * NP + w + 1];
        float sc = g_rs[3 * NP + r * NP + w];
        const float* hb = g_h + (size_t)r * NP * 32;
        float s0 = 0.f;
        int e = beg;
        for (; e + 4 <= end; e += 4) {
            int i0 = g_csr[e], i1 = g_csr[e + 1], i2 = g_csr[e + 2], i3 = g_csr[e + 3];
            float v0 = hb[i0 * 32 + lane];
            float v1 = hb[i1 * 32 + lane];
            float v2 = hb[i2 * 32 + lane];
            float v3 = hb[i3 * 32 + lane];
            s0 += (v0 + v1) + (v2 + v3);
        }
        for (; e < end; ++e) s0 += hb[g_csr[e] * 32 + lane];
        acc = fmaf(sc, s0, acc);
    }
    // lanes 0..15: mean dims; lanes 16..31: log_std dims
    float bias = (lane < 16)
        ? (bmu[lane] + bmu[16 + lane] + bmu[32 + lane])
        : (bls[lane - 16] + bls[lane] + bls[lane + 16]);
    float val = acc + bias;
    float ls  = __shfl_sync(0xffffffffu, val, (lane + 16) & 31);
    uint32_t o0, o1;
    threefry_0_42(0u, (uint32_t)(w * 16 + lane), o0, o1);
    if (lane < 16)
        out[1000000 + w * 16 + lane] = val + jax_normal(o0 ^ o1) * expf(ls);
}

__global__ void score_kernel(const int* __restrict__ ps, const int* __restrict__ pd,
                             const int* __restrict__ ns, const int* __restrict__ nd,
                             float* __restrict__ out) {
    int i = blockIdx.x * 256 + threadIdx.x;
    if (i >= 2 * EPC) return;
    int s, d;
    if (i < EPC) { s = ps[i]; d = pd[i]; }
    else         { s = ns[i - EPC]; d = nd[i - EPC]; }
    const float4* h4 = (const float4*)(out + 1000000);
    float acc = 0.f;
#pragma unroll
    for (int q = 0; q < 4; ++q) {
        float4 a = h4[s * 4 + q], b = h4[d * 4 + q];
        acc += a.x * b.x + a.y * b.y + a.z * b.z + a.w * b.w;
    }
    out[i] = acc;
}

// ---------------- launch ----------------
extern "C" void kernel_launch(void* const* d_in, const int* in_sizes, int n_in,
                              void* d_out, int out_size) {
    const float* x   = (const float*)d_in[0];
    const float* W0  = (const float*)d_in[1];
    const float* b0  = (const float*)d_in[2];
    const float* Wmu = (const float*)d_in[3];
    const float* bmu = (const float*)d_in[4];
    const float* Wls = (const float*)d_in[5];
    const float* bls = (const float*)d_in[6];
    const int*   es  = (const int*)d_in[7];
    const int*   ed  = (const int*)d_in[8];
    const int*   ps  = (const int*)d_in[9];
    const int*   pd  = (const int*)d_in[10];
    const int*   ns  = (const int*)d_in[11];
    const int*   nd  = (const int*)d_in[12];
    float* out = (float*)d_out;

    const int MBLK = (NP + 127) / 128;            // 782
    const int GBLK = (NP * 32 + 255) / 256;       // warp-per-node grids

    zero_kernel         <<<(6 * NP + 255) / 256, 256>>>();
    deg_kernel          <<<(RREL * NE + 255) / 256, 256>>>(es, ed);
    rs_kernel           <<<(6 * NP + 255) / 256, 256>>>();
    scan_blocksum_kernel<<<SCAN_NB, SCAN_BLK>>>();
    scan_spine_kernel   <<<1, 1024>>>();
    scan_apply_kernel   <<<SCAN_NB, SCAN_BLK>>>();
    fill_csr_kernel     <<<(RREL * NE + 255) / 256, 256>>>(es, ed);
    proj1_kernel        <<<dim3(MBLK, RREL), 128>>>(x, W0);
    gather1_kernel      <<<GBLK, 256>>>(b0);
    proj2_kernel        <<<dim3(MBLK, RREL), 128>>>(Wmu, Wls);
    gather2_kernel      <<<GBLK, 256>>>(bmu, bls, out);
    score_kernel        <<<(2 * EPC + 255) / 256, 256>>>(ps, pd, ns, nd, out);
}